// round 3
// baseline (speedup 1.0000x reference)
#include <cuda_runtime.h>
#include <cuda_bf16.h>
#include <cstdint>

// Problem constants (from reference)
#define NN 50000
#define EE 800000
#define KIN 128   // input / hidden channel count (GEMM K is always 128)

// ---------------- scratch (static device globals; no runtime allocation) ---
__device__ float g_Y[NN * 128];     // post-GEMM, dinv[src]-scaled features
__device__ float g_H[NN * 128];     // layer output (post-bias)
__device__ float g_dinv[NN];
__device__ int   g_deg[NN];
__device__ int   g_cursor[NN];
__device__ int   g_rowptr[NN + 1];
__device__ int   g_csrc[EE];
__device__ int   g_bsum[256];
__device__ int   g_boff[256];

// ---------------- preprocessing kernels ------------------------------------

__global__ void init_k(int n) {
    int i = blockIdx.x * blockDim.x + threadIdx.x;
    if (i < n) { g_deg[i] = 1; g_cursor[i] = 0; }   // deg=1 accounts for self-loop
}

__global__ void count_k(const int* __restrict__ ei, int E) {
    int e = blockIdx.x * blockDim.x + threadIdx.x;
    if (e < E) {
        int d = ei[E + e];  // dst row (edge_index is int32: JAX demotes int64)
        atomicAdd(&g_deg[d], 1);
    }
}

__global__ void dinv_k(int n) {
    int i = blockIdx.x * blockDim.x + threadIdx.x;
    if (i < n) g_dinv[i] = rsqrtf((float)g_deg[i]);
}

// block partial sums of (deg-1) over chunks of 1024
__global__ void scan_partial_k(int n) {
    __shared__ int sm[32];
    int tid = threadIdx.x;
    int i = blockIdx.x * 1024 + tid;
    int v = (i < n) ? (g_deg[i] - 1) : 0;
    #pragma unroll
    for (int o = 16; o > 0; o >>= 1) v += __shfl_down_sync(0xffffffffu, v, o);
    int lane = tid & 31, wid = tid >> 5;
    if (lane == 0) sm[wid] = v;
    __syncthreads();
    if (wid == 0) {
        v = sm[lane];
        #pragma unroll
        for (int o = 16; o > 0; o >>= 1) v += __shfl_down_sync(0xffffffffu, v, o);
        if (lane == 0) g_bsum[blockIdx.x] = v;
    }
}

__global__ void scan_bsums_k(int nb) {
    if (threadIdx.x == 0) {
        int acc = 0;
        for (int b = 0; b < nb; b++) { int v = g_bsum[b]; g_boff[b] = acc; acc += v; }
    }
}

__global__ void scan_final_k(int n) {
    __shared__ int sm[1024];
    int tid = threadIdx.x;
    int i = blockIdx.x * 1024 + tid;
    int v = (i < n) ? (g_deg[i] - 1) : 0;
    sm[tid] = v;
    __syncthreads();
    #pragma unroll
    for (int off = 1; off < 1024; off <<= 1) {
        int t = 0;
        if (tid >= off) t = sm[tid - off];
        __syncthreads();
        if (tid >= off) sm[tid] += t;
        __syncthreads();
    }
    int incl = sm[tid];
    if (i < n) {
        g_rowptr[i] = g_boff[blockIdx.x] + incl - v;
        if (i == n - 1) g_rowptr[n] = g_boff[blockIdx.x] + incl;
    }
}

__global__ void fill_k(const int* __restrict__ ei, int E) {
    int e = blockIdx.x * blockDim.x + threadIdx.x;
    if (e < E) {
        int s = ei[e];
        int d = ei[E + e];
        int pos = g_rowptr[d] + atomicAdd(&g_cursor[d], 1);
        g_csrc[pos] = s;
    }
}

// ---------------- GEMM: Y[n,F] = (relu?(A[n,128]) @ W[128,F]) * dinv[row] --
// BM=64, BK=32, 128 threads, 8x(F/16) microtile per thread.
template <int F, bool RELU>
__global__ __launch_bounds__(128)
void gemm_k(const float* __restrict__ A, const float* __restrict__ W, int n) {
    const int BM = 64, BK = 32;
    const int CN = F / 16;                 // cols per thread (8 or 4)
    __shared__ float sA[BM][BK + 1];       // 64 x 33
    __shared__ float sW[BK][F];            // 32 x F

    int tid = threadIdx.x;
    int tx = tid & 15;                     // 0..15 col group
    int ty = tid >> 4;                     // 0..7  row group
    int row0 = blockIdx.x * BM;

    float acc[8][CN];
    #pragma unroll
    for (int i = 0; i < 8; i++)
        #pragma unroll
        for (int j = 0; j < CN; j++) acc[i][j] = 0.0f;

    const int WF4 = F / 4;                 // float4 per W row

    for (int kk = 0; kk < KIN; kk += BK) {
        // load A tile 64x32 = 512 float4, 4 per thread
        #pragma unroll
        for (int p = 0; p < 4; p++) {
            int idx = p * 128 + tid;
            int r = idx >> 3, c4 = idx & 7;
            int grow = row0 + r;
            float4 v = make_float4(0.f, 0.f, 0.f, 0.f);
            if (grow < n)
                v = *(const float4*)(A + (size_t)grow * KIN + kk + c4 * 4);
            if (RELU) {
                v.x = fmaxf(v.x, 0.f); v.y = fmaxf(v.y, 0.f);
                v.z = fmaxf(v.z, 0.f); v.w = fmaxf(v.w, 0.f);
            }
            sA[r][c4 * 4 + 0] = v.x; sA[r][c4 * 4 + 1] = v.y;
            sA[r][c4 * 4 + 2] = v.z; sA[r][c4 * 4 + 3] = v.w;
        }
        // load W tile 32xF: (32*F/4)/128 = F/16 float4 per thread
        #pragma unroll
        for (int p = 0; p < F / 16; p++) {
            int idx = p * 128 + tid;
            int r = idx / WF4, c4 = idx - r * WF4;
            float4 w = *(const float4*)(W + (size_t)(kk + r) * F + c4 * 4);
            *(float4*)&sW[r][c4 * 4] = w;
        }
        __syncthreads();

        #pragma unroll
        for (int k = 0; k < BK; k++) {
            float a[8];
            #pragma unroll
            for (int i = 0; i < 8; i++) a[i] = sA[ty * 8 + i][k];
            float w[CN];
            #pragma unroll
            for (int j4 = 0; j4 < CN / 4; j4++) {
                float4 wv = *(const float4*)&sW[k][tx * CN + j4 * 4];
                w[j4 * 4 + 0] = wv.x; w[j4 * 4 + 1] = wv.y;
                w[j4 * 4 + 2] = wv.z; w[j4 * 4 + 3] = wv.w;
            }
            #pragma unroll
            for (int i = 0; i < 8; i++)
                #pragma unroll
                for (int j = 0; j < CN; j++)
                    acc[i][j] = fmaf(a[i], w[j], acc[i][j]);
        }
        __syncthreads();
    }

    // epilogue: scale by dinv[row], write Y
    #pragma unroll
    for (int i = 0; i < 8; i++) {
        int grow = row0 + ty * 8 + i;
        if (grow < n) {
            float d = g_dinv[grow];
            #pragma unroll
            for (int j4 = 0; j4 < CN / 4; j4++) {
                float4 v;
                v.x = acc[i][j4 * 4 + 0] * d;
                v.y = acc[i][j4 * 4 + 1] * d;
                v.z = acc[i][j4 * 4 + 2] * d;
                v.w = acc[i][j4 * 4 + 3] * d;
                *(float4*)(g_Y + (size_t)grow * F + tx * CN + j4 * 4) = v;
            }
        }
    }
}

// ---------------- aggregation: out[i] = dinv[i]*(Y[i] + sum Y[src]) + b ----
// F=128: 32 lanes per node; F=64: 16 lanes per node. Gather-only, no atomics.
template <int F>
__global__ __launch_bounds__(256)
void agg_k(const float* __restrict__ bias, float* __restrict__ out, int n) {
    const int L = F / 4;                            // lanes per node
    int lane = threadIdx.x & (L - 1);
    int node = (blockIdx.x * blockDim.x + threadIdx.x) / L;
    if (node >= n) return;

    unsigned mask;
    if (L == 32) mask = 0xffffffffu;
    else         mask = 0xffffu << (((threadIdx.x & 31) >> 4) << 4);

    int s = g_rowptr[node];
    int e = g_rowptr[node + 1];

    float4 acc = *(const float4*)(g_Y + (size_t)node * F + lane * 4);  // self loop

    for (int base = s; base < e; base += L) {
        int idx = base + lane;
        int v = (idx < e) ? g_csrc[idx] : 0;
        int cnt = min(L, e - base);
        for (int t = 0; t < cnt; t++) {
            int sc = __shfl_sync(mask, v, t, L);
            float4 yv = *(const float4*)(g_Y + (size_t)sc * F + lane * 4);
            acc.x += yv.x; acc.y += yv.y; acc.z += yv.z; acc.w += yv.w;
        }
    }

    float d = g_dinv[node];
    float4 bb = *(const float4*)(bias + lane * 4);
    float4 o;
    o.x = fmaf(acc.x, d, bb.x);
    o.y = fmaf(acc.y, d, bb.y);
    o.z = fmaf(acc.z, d, bb.z);
    o.w = fmaf(acc.w, d, bb.w);
    *(float4*)(out + (size_t)node * F + lane * 4) = o;
}

// ---------------- launch ----------------------------------------------------

extern "C" void kernel_launch(void* const* d_in, const int* in_sizes, int n_in,
                              void* d_out, int out_size) {
    const float* x  = (const float*)d_in[0];
    const int*   ei = (const int*)d_in[1];   // int32 (JAX demotes int64 w/o x64)
    const float* W1 = (const float*)d_in[2];
    const float* b1 = (const float*)d_in[3];
    const float* W2 = (const float*)d_in[4];
    const float* b2 = (const float*)d_in[5];
    const float* W3 = (const float*)d_in[6];
    const float* b3 = (const float*)d_in[7];
    float* out = (float*)d_out;

    // Device address of g_H for use as a kernel argument.
    float* hH = nullptr;
    cudaGetSymbolAddress((void**)&hH, g_H);

    int n = in_sizes[0] / 128;
    int E = in_sizes[1] / 2;

    int nbN  = (n + 255) / 256;
    int nbE  = (E + 255) / 256;
    int nbS  = (n + 1023) / 1024;

    // --- CSR build (shared by all layers) ---
    init_k<<<nbN, 256>>>(n);
    count_k<<<nbE, 256>>>(ei, E);
    dinv_k<<<nbN, 256>>>(n);
    scan_partial_k<<<nbS, 1024>>>(n);
    scan_bsums_k<<<1, 32>>>(nbS);
    scan_final_k<<<nbS, 1024>>>(n);
    fill_k<<<nbE, 256>>>(ei, E);

    int gGemm = (n + 63) / 64;
    int gAgg128 = ((n * 32) + 255) / 256;  // 8 nodes / block
    int gAgg64  = ((n * 16) + 255) / 256;  // 16 nodes / block

    // --- layer 1: x @ W1 (no relu on input) ---
    gemm_k<128, false><<<gGemm, 128>>>(x, W1, n);
    agg_k<128><<<gAgg128, 256>>>(b1, hH, n);

    // --- layer 2: relu(H) @ W2 ---
    gemm_k<128, true><<<gGemm, 128>>>(hH, W2, n);
    agg_k<128><<<gAgg128, 256>>>(b2, hH, n);

    // --- layer 3: relu(H) @ W3, F=64, output to d_out ---
    gemm_k<64, true><<<gGemm, 128>>>(hH, W3, n);
    agg_k<64><<<gAgg64, 256>>>(b3, out, n);
}

// round 4
// speedup vs baseline: 1.1700x; 1.1700x over previous
#include <cuda_runtime.h>
#include <cuda_bf16.h>
#include <cstdint>

#define NN 50000
#define EE 800000
#define KPAD 136   // bf16 elems per SMEM row (272B) -> conflict-free fragments

// ---------------- scratch (static device globals) --------------------------
__device__ float g_Y[NN * 128];
__device__ float g_H[NN * 128];
__device__ float g_dinv[NN];
__device__ int   g_deg[NN];
__device__ int   g_cursor[NN];
__device__ int   g_rowptr[NN + 1];
__device__ int   g_csrc[EE];
__device__ int   g_bsum[256];
__device__ int   g_boff[256];
// pre-split, pre-transposed weights: [N][K=128] bf16, hi + lo parts
__device__ __nv_bfloat16 g_W1h[128 * 128], g_W1l[128 * 128];
__device__ __nv_bfloat16 g_W2h[128 * 128], g_W2l[128 * 128];
__device__ __nv_bfloat16 g_W3h[64 * 128],  g_W3l[64 * 128];

// ---------------- preprocessing ---------------------------------------------

__global__ void init_k(int n) {
    int i = blockIdx.x * blockDim.x + threadIdx.x;
    if (i < n) { g_deg[i] = 1; g_cursor[i] = 0; }
}

__global__ void count_k(const int* __restrict__ ei, int E) {
    int e = blockIdx.x * blockDim.x + threadIdx.x;
    if (e < E) atomicAdd(&g_deg[ei[E + e]], 1);
}

__global__ void dinv_k(int n) {
    int i = blockIdx.x * blockDim.x + threadIdx.x;
    if (i < n) g_dinv[i] = rsqrtf((float)g_deg[i]);
}

__global__ void scan_partial_k(int n) {
    __shared__ int sm[32];
    int tid = threadIdx.x;
    int i = blockIdx.x * 1024 + tid;
    int v = (i < n) ? (g_deg[i] - 1) : 0;
    #pragma unroll
    for (int o = 16; o > 0; o >>= 1) v += __shfl_down_sync(0xffffffffu, v, o);
    int lane = tid & 31, wid = tid >> 5;
    if (lane == 0) sm[wid] = v;
    __syncthreads();
    if (wid == 0) {
        v = sm[lane];
        #pragma unroll
        for (int o = 16; o > 0; o >>= 1) v += __shfl_down_sync(0xffffffffu, v, o);
        if (lane == 0) g_bsum[blockIdx.x] = v;
    }
}

// one-warp shuffle scan over <=64 block sums (was serial 1-thread loop)
__global__ void scan_bsums_k(int nb) {
    int l = threadIdx.x;
    int v0 = (2 * l     < nb) ? g_bsum[2 * l]     : 0;
    int v1 = (2 * l + 1 < nb) ? g_bsum[2 * l + 1] : 0;
    int s = v0 + v1;
    int inc = s;
    #pragma unroll
    for (int o = 1; o < 32; o <<= 1) {
        int t = __shfl_up_sync(0xffffffffu, inc, o);
        if (l >= o) inc += t;
    }
    int base = inc - s;
    if (2 * l     < nb) g_boff[2 * l]     = base;
    if (2 * l + 1 < nb) g_boff[2 * l + 1] = base + v0;
}

__global__ void scan_final_k(int n) {
    __shared__ int sm[1024];
    int tid = threadIdx.x;
    int i = blockIdx.x * 1024 + tid;
    int v = (i < n) ? (g_deg[i] - 1) : 0;
    sm[tid] = v;
    __syncthreads();
    #pragma unroll
    for (int off = 1; off < 1024; off <<= 1) {
        int t = 0;
        if (tid >= off) t = sm[tid - off];
        __syncthreads();
        if (tid >= off) sm[tid] += t;
        __syncthreads();
    }
    int incl = sm[tid];
    if (i < n) {
        g_rowptr[i] = g_boff[blockIdx.x] + incl - v;
        if (i == n - 1) g_rowptr[n] = g_boff[blockIdx.x] + incl;
    }
}

__global__ void fill_k(const int* __restrict__ ei, int E) {
    int e = blockIdx.x * blockDim.x + threadIdx.x;
    if (e < E) {
        int s = ei[e];
        int d = ei[E + e];
        int pos = g_rowptr[d] + atomicAdd(&g_cursor[d], 1);
        g_csrc[pos] = s;
    }
}

// ---------------- weight conversion: W[K][F] fp32 -> Wt[N][128] bf16 hi/lo --
template <int F>
__global__ void convW_k(const float* __restrict__ W,
                        __nv_bfloat16* __restrict__ Wh,
                        __nv_bfloat16* __restrict__ Wl) {
    int idx = blockIdx.x * blockDim.x + threadIdx.x;
    if (idx >= F * 128) return;
    int nn = idx >> 7, k = idx & 127;
    float v = W[k * F + nn];
    __nv_bfloat16 h = __float2bfloat16(v);
    __nv_bfloat16 l = __float2bfloat16(v - __bfloat162float(h));
    Wh[nn * 128 + k] = h;
    Wl[nn * 128 + k] = l;
}

// ---------------- tensor-core GEMM ------------------------------------------
// Y[n,F] = (relu?(A[n,128]) @ W[128,F]) * dinv[row],  bf16x3 split for fp32.

__device__ __forceinline__ unsigned packbf(float a, float b) {
    __nv_bfloat162 p = __floats2bfloat162_rn(a, b);
    return *reinterpret_cast<unsigned*>(&p);
}

__device__ __forceinline__ void mma_bf16(float& c0, float& c1, float& c2, float& c3,
                                         unsigned a0, unsigned a1, unsigned a2, unsigned a3,
                                         unsigned b0, unsigned b1) {
    asm volatile(
        "mma.sync.aligned.m16n8k16.row.col.f32.bf16.bf16.f32 "
        "{%0,%1,%2,%3}, {%4,%5,%6,%7}, {%8,%9}, {%0,%1,%2,%3};"
        : "+f"(c0), "+f"(c1), "+f"(c2), "+f"(c3)
        : "r"(a0), "r"(a1), "r"(a2), "r"(a3), "r"(b0), "r"(b1));
}

template <int F, bool RELU>
__global__ __launch_bounds__(256)
void gemm_tc(const float* __restrict__ A,
             const __nv_bfloat16* __restrict__ Wh,
             const __nv_bfloat16* __restrict__ Wl, int n) {
    extern __shared__ unsigned char smraw[];
    __nv_bfloat16* sWh = (__nv_bfloat16*)smraw;        // F * KPAD
    __nv_bfloat16* sWl = sWh + F * KPAD;
    __nv_bfloat16* sAh = sWl + F * KPAD;               // 128 * KPAD
    __nv_bfloat16* sAl = sAh + 128 * KPAD;

    const int NT = F / 8;                              // n-tiles per warp
    int tid = threadIdx.x;
    int wid = tid >> 5, lane = tid & 31;
    int g = lane >> 2, t = lane & 3;

    // stage W (hi+lo) into padded SMEM, once per block
    {
        const unsigned* gwh = (const unsigned*)Wh;
        const unsigned* gwl = (const unsigned*)Wl;
        for (int i = tid; i < F * 64; i += 256) {
            int r = i >> 6, c = i & 63;
            ((unsigned*)(sWh + r * KPAD))[c] = gwh[i];
            ((unsigned*)(sWl + r * KPAD))[c] = gwl[i];
        }
    }

    int ntiles = (n + 127) >> 7;
    for (int tile = blockIdx.x; tile < ntiles; tile += gridDim.x) {
        __syncthreads();   // previous tile's reads done (also orders W on iter 0)
        int r0 = tile * 128;

        // load + (relu) + split A tile: 128 x 128 fp32 -> bf16 hi/lo
        for (int i = tid; i < 4096; i += 256) {
            int r = i >> 5, c4 = i & 31;
            int row = r0 + r;
            float4 v = make_float4(0.f, 0.f, 0.f, 0.f);
            if (row < n) v = *(const float4*)(A + (size_t)row * 128 + c4 * 4);
            if (RELU) {
                v.x = fmaxf(v.x, 0.f); v.y = fmaxf(v.y, 0.f);
                v.z = fmaxf(v.z, 0.f); v.w = fmaxf(v.w, 0.f);
            }
            __nv_bfloat16 h0 = __float2bfloat16(v.x), h1 = __float2bfloat16(v.y);
            __nv_bfloat16 h2 = __float2bfloat16(v.z), h3 = __float2bfloat16(v.w);
            float l0 = v.x - __bfloat162float(h0), l1 = v.y - __bfloat162float(h1);
            float l2 = v.z - __bfloat162float(h2), l3 = v.w - __bfloat162float(h3);
            unsigned h01, h23;
            { __nv_bfloat162 p0 = {h0, h1}; h01 = *reinterpret_cast<unsigned*>(&p0);
              __nv_bfloat162 p1 = {h2, h3}; h23 = *reinterpret_cast<unsigned*>(&p1); }
            unsigned l01 = packbf(l0, l1), l23 = packbf(l2, l3);
            *reinterpret_cast<uint2*>(sAh + r * KPAD + c4 * 4) = make_uint2(h01, h23);
            *reinterpret_cast<uint2*>(sAl + r * KPAD + c4 * 4) = make_uint2(l01, l23);
        }
        __syncthreads();

        float acc[NT][4];
        #pragma unroll
        for (int j = 0; j < NT; j++) {
            acc[j][0] = 0.f; acc[j][1] = 0.f; acc[j][2] = 0.f; acc[j][3] = 0.f;
        }

        int arow = wid * 16;
        #pragma unroll
        for (int kk = 0; kk < 128; kk += 16) {
            unsigned a0h = *(const unsigned*)(sAh + (arow + g)     * KPAD + kk + 2 * t);
            unsigned a1h = *(const unsigned*)(sAh + (arow + g + 8) * KPAD + kk + 2 * t);
            unsigned a2h = *(const unsigned*)(sAh + (arow + g)     * KPAD + kk + 8 + 2 * t);
            unsigned a3h = *(const unsigned*)(sAh + (arow + g + 8) * KPAD + kk + 8 + 2 * t);
            unsigned a0l = *(const unsigned*)(sAl + (arow + g)     * KPAD + kk + 2 * t);
            unsigned a1l = *(const unsigned*)(sAl + (arow + g + 8) * KPAD + kk + 2 * t);
            unsigned a2l = *(const unsigned*)(sAl + (arow + g)     * KPAD + kk + 8 + 2 * t);
            unsigned a3l = *(const unsigned*)(sAl + (arow + g + 8) * KPAD + kk + 8 + 2 * t);
            #pragma unroll
            for (int j = 0; j < NT; j++) {
                int bn = j * 8 + g;
                unsigned b0h = *(const unsigned*)(sWh + bn * KPAD + kk + 2 * t);
                unsigned b1h = *(const unsigned*)(sWh + bn * KPAD + kk + 8 + 2 * t);
                unsigned b0l = *(const unsigned*)(sWl + bn * KPAD + kk + 2 * t);
                unsigned b1l = *(const unsigned*)(sWl + bn * KPAD + kk + 8 + 2 * t);
                mma_bf16(acc[j][0], acc[j][1], acc[j][2], acc[j][3],
                         a0h, a1h, a2h, a3h, b0h, b1h);        // Ah * Wh
                mma_bf16(acc[j][0], acc[j][1], acc[j][2], acc[j][3],
                         a0h, a1h, a2h, a3h, b0l, b1l);        // Ah * Wl
                mma_bf16(acc[j][0], acc[j][1], acc[j][2], acc[j][3],
                         a0l, a1l, a2l, a3l, b0h, b1h);        // Al * Wh
            }
        }

        // epilogue: scale by dinv[row], write Y
        int row0 = r0 + arow + g;
        int row1 = row0 + 8;
        float d0 = (row0 < n) ? g_dinv[row0] : 0.f;
        float d1 = (row1 < n) ? g_dinv[row1] : 0.f;
        #pragma unroll
        for (int j = 0; j < NT; j++) {
            int col = j * 8 + 2 * t;
            if (row0 < n) {
                float2 o = make_float2(acc[j][0] * d0, acc[j][1] * d0);
                *(float2*)(g_Y + (size_t)row0 * F + col) = o;
            }
            if (row1 < n) {
                float2 o = make_float2(acc[j][2] * d1, acc[j][3] * d1);
                *(float2*)(g_Y + (size_t)row1 * F + col) = o;
            }
        }
    }
}

// ---------------- aggregation: out[i] = dinv[i]*(Y[i] + sum Y[src]) + b ----
template <int F>
__global__ __launch_bounds__(256)
void agg_k(const float* __restrict__ bias, float* __restrict__ out, int n) {
    const int L = F / 4;
    int lane = threadIdx.x & (L - 1);
    int node = (blockIdx.x * blockDim.x + threadIdx.x) / L;
    if (node >= n) return;

    unsigned mask;
    if (L == 32) mask = 0xffffffffu;
    else         mask = 0xffffu << (((threadIdx.x & 31) >> 4) << 4);

    int s = g_rowptr[node];
    int e = g_rowptr[node + 1];

    float4 acc = *(const float4*)(g_Y + (size_t)node * F + lane * 4);

    for (int base = s; base < e; base += L) {
        int idx = base + lane;
        int v = (idx < e) ? g_csrc[idx] : 0;
        int cnt = min(L, e - base);
        for (int tt = 0; tt < cnt; tt++) {
            int sc = __shfl_sync(mask, v, tt, L);
            float4 yv = *(const float4*)(g_Y + (size_t)sc * F + lane * 4);
            acc.x += yv.x; acc.y += yv.y; acc.z += yv.z; acc.w += yv.w;
        }
    }

    float d = g_dinv[node];
    float4 bb = *(const float4*)(bias + lane * 4);
    float4 o;
    o.x = fmaf(acc.x, d, bb.x);
    o.y = fmaf(acc.y, d, bb.y);
    o.z = fmaf(acc.z, d, bb.z);
    o.w = fmaf(acc.w, d, bb.w);
    *(float4*)(out + (size_t)node * F + lane * 4) = o;
}

// ---------------- launch -----------------------------------------------------

extern "C" void kernel_launch(void* const* d_in, const int* in_sizes, int n_in,
                              void* d_out, int out_size) {
    const float* x  = (const float*)d_in[0];
    const int*   ei = (const int*)d_in[1];   // int32
    const float* W1 = (const float*)d_in[2];
    const float* b1 = (const float*)d_in[3];
    const float* W2 = (const float*)d_in[4];
    const float* b2 = (const float*)d_in[5];
    const float* W3 = (const float*)d_in[6];
    const float* b3 = (const float*)d_in[7];
    float* out = (float*)d_out;

    float* hH = nullptr;
    cudaGetSymbolAddress((void**)&hH, g_H);
    __nv_bfloat16 *w1h, *w1l, *w2h, *w2l, *w3h, *w3l;
    cudaGetSymbolAddress((void**)&w1h, g_W1h);
    cudaGetSymbolAddress((void**)&w1l, g_W1l);
    cudaGetSymbolAddress((void**)&w2h, g_W2h);
    cudaGetSymbolAddress((void**)&w2l, g_W2l);
    cudaGetSymbolAddress((void**)&w3h, g_W3h);
    cudaGetSymbolAddress((void**)&w3l, g_W3l);

    int n = in_sizes[0] / 128;
    int E = in_sizes[1] / 2;

    const int SMEM128 = 2 * KPAD * (2 * 128 + 2 * 128);  // 139264 B
    const int SMEM64  = 2 * KPAD * (2 * 64  + 2 * 128);  // 104448 B
    cudaFuncSetAttribute(gemm_tc<128, false>, cudaFuncAttributeMaxDynamicSharedMemorySize, SMEM128);
    cudaFuncSetAttribute(gemm_tc<128, true>,  cudaFuncAttributeMaxDynamicSharedMemorySize, SMEM128);
    cudaFuncSetAttribute(gemm_tc<64,  true>,  cudaFuncAttributeMaxDynamicSharedMemorySize, SMEM64);

    int nbN = (n + 255) / 256;
    int nbE = (E + 255) / 256;
    int nbS = (n + 1023) / 1024;

    // --- CSR build ---
    init_k<<<nbN, 256>>>(n);
    count_k<<<nbE, 256>>>(ei, E);
    dinv_k<<<nbN, 256>>>(n);
    scan_partial_k<<<nbS, 1024>>>(n);
    scan_bsums_k<<<1, 32>>>(nbS);
    scan_final_k<<<nbS, 1024>>>(n);
    fill_k<<<nbE, 256>>>(ei, E);

    // --- weight conversion (split + transpose) ---
    convW_k<128><<<64, 256>>>(W1, w1h, w1l);
    convW_k<128><<<64, 256>>>(W2, w2h, w2l);
    convW_k<64><<<32, 256>>>(W3, w3h, w3l);

    int gAgg128 = ((n * 32) + 255) / 256;
    int gAgg64  = ((n * 16) + 255) / 256;

    // --- layer 1 ---
    gemm_tc<128, false><<<148, 256, SMEM128>>>(x, w1h, w1l, n);
    agg_k<128><<<gAgg128, 256>>>(b1, hH, n);

    // --- layer 2 ---
    gemm_tc<128, true><<<148, 256, SMEM128>>>(hH, w2h, w2l, n);
    agg_k<128><<<gAgg128, 256>>>(b2, hH, n);

    // --- layer 3 ---
    gemm_tc<64, true><<<148, 256, SMEM64>>>(hH, w3h, w3l, n);
    agg_k<64><<<gAgg64, 256>>>(b3, out, n);
}

// round 5
// speedup vs baseline: 1.2085x; 1.0330x over previous
#include <cuda_runtime.h>
#include <cuda_bf16.h>
#include <cstdint>

#define NN 50000
#define EE 800000
#define KPAD 136   // bf16 elems per SMEM row (272B) -> conflict-free fragments

// ---------------- scratch (static device globals) --------------------------
__device__ float g_Y[NN * 128];
__device__ float g_H[NN * 128];
__device__ float g_dinv[NN];
__device__ int   g_deg[NN];
__device__ int   g_cursor[NN];
__device__ int   g_rowptr[NN + 1];
__device__ int   g_csrc[EE];
__device__ int   g_bsum[256];
__device__ int   g_boff[256];
// pre-split, pre-transposed weights: [N][K=128] bf16, hi + lo parts
__device__ __nv_bfloat16 g_W1h[128 * 128], g_W1l[128 * 128];
__device__ __nv_bfloat16 g_W2h[128 * 128], g_W2l[128 * 128];
__device__ __nv_bfloat16 g_W3h[64 * 128],  g_W3l[64 * 128];

// ---------------- preprocessing ---------------------------------------------

__global__ void init_k(int n) {
    int i = blockIdx.x * blockDim.x + threadIdx.x;
    if (i < n) g_deg[i] = 1;   // self-loop
}

__global__ void count_k(const int* __restrict__ ei, int E) {
    int e = blockIdx.x * blockDim.x + threadIdx.x;
    if (e < E) atomicAdd(&g_deg[ei[E + e]], 1);
}

// fused: dinv + per-1024-block partial sums of (deg-1)
__global__ void scan_partial_k(int n) {
    __shared__ int sm[32];
    int tid = threadIdx.x;
    int i = blockIdx.x * 1024 + tid;
    int v = 0;
    if (i < n) {
        int d = g_deg[i];
        g_dinv[i] = rsqrtf((float)d);
        v = d - 1;
    }
    int vv = v;
    #pragma unroll
    for (int o = 16; o > 0; o >>= 1) vv += __shfl_down_sync(0xffffffffu, vv, o);
    int lane = tid & 31, wid = tid >> 5;
    if (lane == 0) sm[wid] = vv;
    __syncthreads();
    if (wid == 0) {
        vv = sm[lane];
        #pragma unroll
        for (int o = 16; o > 0; o >>= 1) vv += __shfl_down_sync(0xffffffffu, vv, o);
        if (lane == 0) g_bsum[blockIdx.x] = vv;
    }
}

// one-warp shuffle scan over <=64 block sums
__global__ void scan_bsums_k(int nb) {
    int l = threadIdx.x;
    int v0 = (2 * l     < nb) ? g_bsum[2 * l]     : 0;
    int v1 = (2 * l + 1 < nb) ? g_bsum[2 * l + 1] : 0;
    int s = v0 + v1;
    int inc = s;
    #pragma unroll
    for (int o = 1; o < 32; o <<= 1) {
        int t = __shfl_up_sync(0xffffffffu, inc, o);
        if (l >= o) inc += t;
    }
    int base = inc - s;
    if (2 * l     < nb) g_boff[2 * l]     = base;
    if (2 * l + 1 < nb) g_boff[2 * l + 1] = base + v0;
}

// writes rowptr AND the fill cursor copy
__global__ void scan_final_k(int n) {
    __shared__ int sm[1024];
    int tid = threadIdx.x;
    int i = blockIdx.x * 1024 + tid;
    int v = (i < n) ? (g_deg[i] - 1) : 0;
    sm[tid] = v;
    __syncthreads();
    #pragma unroll
    for (int off = 1; off < 1024; off <<= 1) {
        int t = 0;
        if (tid >= off) t = sm[tid - off];
        __syncthreads();
        if (tid >= off) sm[tid] += t;
        __syncthreads();
    }
    int incl = sm[tid];
    if (i < n) {
        int rp = g_boff[blockIdx.x] + incl - v;
        g_rowptr[i] = rp;
        g_cursor[i] = rp;
        if (i == n - 1) g_rowptr[n] = g_boff[blockIdx.x] + incl;
    }
}

__global__ void fill_k(const int* __restrict__ ei, int E) {
    int e = blockIdx.x * blockDim.x + threadIdx.x;
    if (e < E) {
        int s = ei[e];
        int d = ei[E + e];
        int pos = atomicAdd(&g_cursor[d], 1);
        g_csrc[pos] = s;
    }
}

// ---------------- fused weight conversion (all 3 layers) --------------------
// W[K][F] fp32 -> Wt[N][128] bf16 hi/lo
__device__ __forceinline__ void conv_one(const float* W, __nv_bfloat16* Wh,
                                         __nv_bfloat16* Wl, int F, int idx) {
    int nn = idx >> 7, k = idx & 127;
    float v = W[k * F + nn];
    __nv_bfloat16 h = __float2bfloat16(v);
    __nv_bfloat16 l = __float2bfloat16(v - __bfloat162float(h));
    Wh[nn * 128 + k] = h;
    Wl[nn * 128 + k] = l;
}

__global__ void convW_all_k(const float* __restrict__ W1,
                            const float* __restrict__ W2,
                            const float* __restrict__ W3) {
    int idx = blockIdx.x * blockDim.x + threadIdx.x;
    if (idx < 16384)       conv_one(W1, g_W1h, g_W1l, 128, idx);
    else if (idx < 32768)  conv_one(W2, g_W2h, g_W2l, 128, idx - 16384);
    else if (idx < 40960)  conv_one(W3, g_W3h, g_W3l, 64,  idx - 32768);
}

// ---------------- tensor-core GEMM ------------------------------------------
// Y[n,F] = (relu?(A[n,128]) @ W[128,F]) * dinv[row],  bf16x3 split for fp32.
// Warp tiling 4(M) x 2(N): Mw=32 rows, Nw=F/2 cols per warp.

__device__ __forceinline__ unsigned packbf(float a, float b) {
    __nv_bfloat162 p = __floats2bfloat162_rn(a, b);
    return *reinterpret_cast<unsigned*>(&p);
}

__device__ __forceinline__ void mma_bf16(float* c,
                                         unsigned a0, unsigned a1, unsigned a2, unsigned a3,
                                         unsigned b0, unsigned b1) {
    asm volatile(
        "mma.sync.aligned.m16n8k16.row.col.f32.bf16.bf16.f32 "
        "{%0,%1,%2,%3}, {%4,%5,%6,%7}, {%8,%9}, {%0,%1,%2,%3};"
        : "+f"(c[0]), "+f"(c[1]), "+f"(c[2]), "+f"(c[3])
        : "r"(a0), "r"(a1), "r"(a2), "r"(a3), "r"(b0), "r"(b1));
}

template <int F, bool RELU>
__global__ __launch_bounds__(256)
void gemm_tc(const float* __restrict__ A,
             const __nv_bfloat16* __restrict__ Wh,
             const __nv_bfloat16* __restrict__ Wl, int n) {
    extern __shared__ unsigned char smraw[];
    __nv_bfloat16* sWh = (__nv_bfloat16*)smraw;        // F * KPAD
    __nv_bfloat16* sWl = sWh + F * KPAD;
    __nv_bfloat16* sAh = sWl + F * KPAD;               // 128 * KPAD
    __nv_bfloat16* sAl = sAh + 128 * KPAD;

    const int NT = F / 16;                             // 8-wide n-tiles per warp
    int tid = threadIdx.x;
    int wid = tid >> 5, lane = tid & 31;
    int g = lane >> 2, t = lane & 3;
    int wm = wid >> 1;                                 // 0..3 (M)
    int wn = wid & 1;                                  // 0..1 (N)
    int arow = wm * 32;
    int bcol0 = wn * (F / 2);

    // stage W (hi+lo) into padded SMEM, once per block
    {
        const unsigned* gwh = (const unsigned*)Wh;
        const unsigned* gwl = (const unsigned*)Wl;
        for (int i = tid; i < F * 64; i += 256) {
            int r = i >> 6, c = i & 63;
            ((unsigned*)(sWh + r * KPAD))[c] = gwh[i];
            ((unsigned*)(sWl + r * KPAD))[c] = gwl[i];
        }
    }

    int ntiles = (n + 127) >> 7;
    for (int tile = blockIdx.x; tile < ntiles; tile += gridDim.x) {
        __syncthreads();   // previous tile's reads done (also orders W on iter 0)
        int r0 = tile * 128;

        // load + (relu) + split A tile: 128 x 128 fp32 -> bf16 hi/lo
        for (int i = tid; i < 4096; i += 256) {
            int r = i >> 5, c4 = i & 31;
            int row = r0 + r;
            float4 v = make_float4(0.f, 0.f, 0.f, 0.f);
            if (row < n) v = *(const float4*)(A + (size_t)row * 128 + c4 * 4);
            if (RELU) {
                v.x = fmaxf(v.x, 0.f); v.y = fmaxf(v.y, 0.f);
                v.z = fmaxf(v.z, 0.f); v.w = fmaxf(v.w, 0.f);
            }
            __nv_bfloat16 h0 = __float2bfloat16(v.x), h1 = __float2bfloat16(v.y);
            __nv_bfloat16 h2 = __float2bfloat16(v.z), h3 = __float2bfloat16(v.w);
            float l0 = v.x - __bfloat162float(h0), l1 = v.y - __bfloat162float(h1);
            float l2 = v.z - __bfloat162float(h2), l3 = v.w - __bfloat162float(h3);
            unsigned h01, h23;
            { __nv_bfloat162 p0 = {h0, h1}; h01 = *reinterpret_cast<unsigned*>(&p0);
              __nv_bfloat162 p1 = {h2, h3}; h23 = *reinterpret_cast<unsigned*>(&p1); }
            unsigned l01 = packbf(l0, l1), l23 = packbf(l2, l3);
            *reinterpret_cast<uint2*>(sAh + r * KPAD + c4 * 4) = make_uint2(h01, h23);
            *reinterpret_cast<uint2*>(sAl + r * KPAD + c4 * 4) = make_uint2(l01, l23);
        }
        __syncthreads();

        float acc[2][NT][4];
        #pragma unroll
        for (int rb = 0; rb < 2; rb++)
            #pragma unroll
            for (int j = 0; j < NT; j++) {
                acc[rb][j][0] = 0.f; acc[rb][j][1] = 0.f;
                acc[rb][j][2] = 0.f; acc[rb][j][3] = 0.f;
            }

        #pragma unroll
        for (int kk = 0; kk < 128; kk += 16) {
            unsigned ah[2][4], al[2][4];
            #pragma unroll
            for (int rb = 0; rb < 2; rb++) {
                int br = arow + rb * 16;
                ah[rb][0] = *(const unsigned*)(sAh + (br + g)     * KPAD + kk + 2 * t);
                ah[rb][1] = *(const unsigned*)(sAh + (br + g + 8) * KPAD + kk + 2 * t);
                ah[rb][2] = *(const unsigned*)(sAh + (br + g)     * KPAD + kk + 8 + 2 * t);
                ah[rb][3] = *(const unsigned*)(sAh + (br + g + 8) * KPAD + kk + 8 + 2 * t);
                al[rb][0] = *(const unsigned*)(sAl + (br + g)     * KPAD + kk + 2 * t);
                al[rb][1] = *(const unsigned*)(sAl + (br + g + 8) * KPAD + kk + 2 * t);
                al[rb][2] = *(const unsigned*)(sAl + (br + g)     * KPAD + kk + 8 + 2 * t);
                al[rb][3] = *(const unsigned*)(sAl + (br + g + 8) * KPAD + kk + 8 + 2 * t);
            }
            #pragma unroll
            for (int j = 0; j < NT; j++) {
                int bn = bcol0 + j * 8 + g;
                unsigned b0h = *(const unsigned*)(sWh + bn * KPAD + kk + 2 * t);
                unsigned b1h = *(const unsigned*)(sWh + bn * KPAD + kk + 8 + 2 * t);
                unsigned b0l = *(const unsigned*)(sWl + bn * KPAD + kk + 2 * t);
                unsigned b1l = *(const unsigned*)(sWl + bn * KPAD + kk + 8 + 2 * t);
                #pragma unroll
                for (int rb = 0; rb < 2; rb++) {
                    mma_bf16(acc[rb][j], ah[rb][0], ah[rb][1], ah[rb][2], ah[rb][3], b0h, b1h);
                    mma_bf16(acc[rb][j], ah[rb][0], ah[rb][1], ah[rb][2], ah[rb][3], b0l, b1l);
                    mma_bf16(acc[rb][j], al[rb][0], al[rb][1], al[rb][2], al[rb][3], b0h, b1h);
                }
            }
        }

        // epilogue: scale by dinv[row], write Y
        #pragma unroll
        for (int rb = 0; rb < 2; rb++) {
            int row0 = r0 + arow + rb * 16 + g;
            int row1 = row0 + 8;
            float d0 = (row0 < n) ? g_dinv[row0] : 0.f;
            float d1 = (row1 < n) ? g_dinv[row1] : 0.f;
            #pragma unroll
            for (int j = 0; j < NT; j++) {
                int col = bcol0 + j * 8 + 2 * t;
                if (row0 < n) {
                    float2 o = make_float2(acc[rb][j][0] * d0, acc[rb][j][1] * d0);
                    *(float2*)(g_Y + (size_t)row0 * F + col) = o;
                }
                if (row1 < n) {
                    float2 o = make_float2(acc[rb][j][2] * d1, acc[rb][j][3] * d1);
                    *(float2*)(g_Y + (size_t)row1 * F + col) = o;
                }
            }
        }
    }
}

// ---------------- aggregation: out[i] = dinv[i]*(Y[i] + sum Y[src]) + b ----
// 4-way unrolled gather with 4 independent accumulators (MLP~4).
template <int F>
__global__ __launch_bounds__(256)
void agg_k(const float* __restrict__ bias, float* __restrict__ out, int n) {
    const int L = F / 4;
    int lane = threadIdx.x & (L - 1);
    int node = (blockIdx.x * blockDim.x + threadIdx.x) / L;
    if (node >= n) return;

    unsigned mask;
    if (L == 32) mask = 0xffffffffu;
    else         mask = 0xffffu << (((threadIdx.x & 31) >> 4) << 4);

    int s = g_rowptr[node];
    int e = g_rowptr[node + 1];

    float4 a0 = *(const float4*)(g_Y + (size_t)node * F + lane * 4);  // self loop
    float4 a1 = make_float4(0.f, 0.f, 0.f, 0.f);
    float4 a2 = make_float4(0.f, 0.f, 0.f, 0.f);
    float4 a3 = make_float4(0.f, 0.f, 0.f, 0.f);

    for (int base = s; base < e; base += L) {
        int idx = base + lane;
        int v = (idx < e) ? g_csrc[idx] : 0;
        int cnt = min(L, e - base);
        int tt = 0;
        for (; tt + 4 <= cnt; tt += 4) {
            int s0 = __shfl_sync(mask, v, tt,     L);
            int s1 = __shfl_sync(mask, v, tt + 1, L);
            int s2 = __shfl_sync(mask, v, tt + 2, L);
            int s3 = __shfl_sync(mask, v, tt + 3, L);
            float4 y0 = *(const float4*)(g_Y + (size_t)s0 * F + lane * 4);
            float4 y1 = *(const float4*)(g_Y + (size_t)s1 * F + lane * 4);
            float4 y2 = *(const float4*)(g_Y + (size_t)s2 * F + lane * 4);
            float4 y3 = *(const float4*)(g_Y + (size_t)s3 * F + lane * 4);
            a0.x += y0.x; a0.y += y0.y; a0.z += y0.z; a0.w += y0.w;
            a1.x += y1.x; a1.y += y1.y; a1.z += y1.z; a1.w += y1.w;
            a2.x += y2.x; a2.y += y2.y; a2.z += y2.z; a2.w += y2.w;
            a3.x += y3.x; a3.y += y3.y; a3.z += y3.z; a3.w += y3.w;
        }
        for (; tt < cnt; tt++) {
            int sc = __shfl_sync(mask, v, tt, L);
            float4 yv = *(const float4*)(g_Y + (size_t)sc * F + lane * 4);
            a0.x += yv.x; a0.y += yv.y; a0.z += yv.z; a0.w += yv.w;
        }
    }

    float4 acc;
    acc.x = (a0.x + a1.x) + (a2.x + a3.x);
    acc.y = (a0.y + a1.y) + (a2.y + a3.y);
    acc.z = (a0.z + a1.z) + (a2.z + a3.z);
    acc.w = (a0.w + a1.w) + (a2.w + a3.w);

    float d = g_dinv[node];
    float4 bb = *(const float4*)(bias + lane * 4);
    float4 o;
    o.x = fmaf(acc.x, d, bb.x);
    o.y = fmaf(acc.y, d, bb.y);
    o.z = fmaf(acc.z, d, bb.z);
    o.w = fmaf(acc.w, d, bb.w);
    *(float4*)(out + (size_t)node * F + lane * 4) = o;
}

// ---------------- launch -----------------------------------------------------

extern "C" void kernel_launch(void* const* d_in, const int* in_sizes, int n_in,
                              void* d_out, int out_size) {
    const float* x  = (const float*)d_in[0];
    const int*   ei = (const int*)d_in[1];   // int32
    const float* W1 = (const float*)d_in[2];
    const float* b1 = (const float*)d_in[3];
    const float* W2 = (const float*)d_in[4];
    const float* b2 = (const float*)d_in[5];
    const float* W3 = (const float*)d_in[6];
    const float* b3 = (const float*)d_in[7];
    float* out = (float*)d_out;

    float* hH = nullptr;
    cudaGetSymbolAddress((void**)&hH, g_H);
    __nv_bfloat16 *w1h, *w1l, *w2h, *w2l, *w3h, *w3l;
    cudaGetSymbolAddress((void**)&w1h, g_W1h);
    cudaGetSymbolAddress((void**)&w1l, g_W1l);
    cudaGetSymbolAddress((void**)&w2h, g_W2h);
    cudaGetSymbolAddress((void**)&w2l, g_W2l);
    cudaGetSymbolAddress((void**)&w3h, g_W3h);
    cudaGetSymbolAddress((void**)&w3l, g_W3l);

    int n = in_sizes[0] / 128;
    int E = in_sizes[1] / 2;

    const int SMEM128 = 4 * KPAD * (128 + 128);  // 139264 B
    const int SMEM64  = 4 * KPAD * (64  + 128);  // 104448 B
    cudaFuncSetAttribute(gemm_tc<128, false>, cudaFuncAttributeMaxDynamicSharedMemorySize, SMEM128);
    cudaFuncSetAttribute(gemm_tc<128, true>,  cudaFuncAttributeMaxDynamicSharedMemorySize, SMEM128);
    cudaFuncSetAttribute(gemm_tc<64,  true>,  cudaFuncAttributeMaxDynamicSharedMemorySize, SMEM64);

    int nbN = (n + 255) / 256;
    int nbE = (E + 255) / 256;
    int nbS = (n + 1023) / 1024;

    // --- CSR build (fused) ---
    init_k<<<nbN, 256>>>(n);
    count_k<<<nbE, 256>>>(ei, E);
    scan_partial_k<<<nbS, 1024>>>(n);      // + dinv
    scan_bsums_k<<<1, 32>>>(nbS);
    scan_final_k<<<nbS, 1024>>>(n);        // + cursor copy
    fill_k<<<nbE, 256>>>(ei, E);

    // --- weight conversion (all 3 fused) ---
    convW_all_k<<<160, 256>>>(W1, W2, W3);

    int gAgg128 = ((n * 32) + 255) / 256;
    int gAgg64  = ((n * 16) + 255) / 256;

    // --- layer 1 ---
    gemm_tc<128, false><<<148, 256, SMEM128>>>(x, w1h, w1l, n);
    agg_k<128><<<gAgg128, 256>>>(b1, hH, n);

    // --- layer 2 ---
    gemm_tc<128, true><<<148, 256, SMEM128>>>(hH, w2h, w2l, n);
    agg_k<128><<<gAgg128, 256>>>(b2, hH, n);

    // --- layer 3 ---
    gemm_tc<64, true><<<148, 256, SMEM64>>>(hH, w3h, w3l, n);
    agg_k<64><<<gAgg64, 256>>>(b3, out, n);
}

// round 6
// speedup vs baseline: 1.2192x; 1.0088x over previous
#include <cuda_runtime.h>
#include <cuda_bf16.h>
#include <cstdint>

#define NN 50000
#define EE 800000
#define KPAD 136   // bf16 elems per SMEM row (272B) -> conflict-free fragments

// ---------------- scratch (static device globals) --------------------------
__device__ float g_Y[NN * 128];
__device__ float g_H[NN * 128];
__device__ float g_dinv[NN];
__device__ int   g_deg[NN];        // edge-only degree; zeroed by scan_final for next replay
__device__ int   g_cursor[NN];
__device__ int   g_rowptr[NN + 1];
__device__ int   g_csrc[EE];
__device__ int   g_bsum[64];
// pre-split, pre-transposed weights: [N][K=128] bf16, hi + lo parts
__device__ __nv_bfloat16 g_W1h[128 * 128], g_W1l[128 * 128];
__device__ __nv_bfloat16 g_W2h[128 * 128], g_W2l[128 * 128];
__device__ __nv_bfloat16 g_W3h[64 * 128],  g_W3l[64 * 128];

// ---------------- preprocessing ---------------------------------------------

// deg starts at 0 (static zero-init on first run; scan_final re-zeroes each run)
__global__ void count_k(const int* __restrict__ ei, int E) {
    int e = blockIdx.x * blockDim.x + threadIdx.x;
    if (e < E) atomicAdd(&g_deg[ei[E + e]], 1);
}

__device__ __forceinline__ void conv_one(const float* W, __nv_bfloat16* Wh,
                                         __nv_bfloat16* Wl, int F, int idx) {
    int nn = idx >> 7, k = idx & 127;
    float v = W[k * F + nn];
    __nv_bfloat16 h = __float2bfloat16(v);
    __nv_bfloat16 l = __float2bfloat16(v - __bfloat162float(h));
    Wh[nn * 128 + k] = h;
    Wl[nn * 128 + k] = l;
}

// blocks [0, nbS): dinv + per-1024-chunk partial sums of edge-degree
// blocks [nbS, nbS+CONVB): weight split/transpose for all 3 layers
#define CONVB 10
__global__ void scanconv_k(int n, int nbS,
                           const float* __restrict__ W1,
                           const float* __restrict__ W2,
                           const float* __restrict__ W3) {
    int bid = blockIdx.x;
    int tid = threadIdx.x;
    if (bid >= nbS) {
        // weight conversion: 40960 elements, stride loop
        for (int idx = (bid - nbS) * 1024 + tid; idx < 40960; idx += CONVB * 1024) {
            if (idx < 16384)       conv_one(W1, g_W1h, g_W1l, 128, idx);
            else if (idx < 32768)  conv_one(W2, g_W2h, g_W2l, 128, idx - 16384);
            else                   conv_one(W3, g_W3h, g_W3l, 64,  idx - 32768);
        }
        return;
    }
    __shared__ int sm[32];
    int i = bid * 1024 + tid;
    int v = 0;
    if (i < n) {
        v = g_deg[i];                       // edge-only degree
        g_dinv[i] = rsqrtf((float)(v + 1)); // +1 self-loop
    }
    int vv = v;
    #pragma unroll
    for (int o = 16; o > 0; o >>= 1) vv += __shfl_down_sync(0xffffffffu, vv, o);
    int lane = tid & 31, wid = tid >> 5;
    if (lane == 0) sm[wid] = vv;
    __syncthreads();
    if (wid == 0) {
        vv = sm[lane];
        #pragma unroll
        for (int o = 16; o > 0; o >>= 1) vv += __shfl_down_sync(0xffffffffu, vv, o);
        if (lane == 0) g_bsum[bid] = vv;
    }
}

// rowptr + cursor + zero deg; each block computes its own bsum-prefix (nbS<=64)
__global__ void scan_final_k(int n, int nbS) {
    __shared__ int sm[1024];
    __shared__ int s_off;
    int tid = threadIdx.x;
    int bid = blockIdx.x;
    int i = bid * 1024 + tid;

    if (tid < 32) {
        int a = (tid      < bid) ? g_bsum[tid]      : 0;
        int b = (tid + 32 < bid) ? g_bsum[tid + 32] : 0;
        int s = a + b;
        #pragma unroll
        for (int o = 16; o > 0; o >>= 1) s += __shfl_down_sync(0xffffffffu, s, o);
        if (tid == 0) s_off = s;
    }

    int v = 0;
    if (i < n) {
        v = g_deg[i];
        g_deg[i] = 0;                        // reset for next graph replay
    }
    sm[tid] = v;
    __syncthreads();
    #pragma unroll
    for (int off = 1; off < 1024; off <<= 1) {
        int t = 0;
        if (tid >= off) t = sm[tid - off];
        __syncthreads();
        if (tid >= off) sm[tid] += t;
        __syncthreads();
    }
    int incl = sm[tid];
    if (i < n) {
        int rp = s_off + incl - v;
        g_rowptr[i] = rp;
        g_cursor[i] = rp;
        if (i == n - 1) g_rowptr[n] = s_off + incl;
    }
}

__global__ void fill_k(const int* __restrict__ ei, int E) {
    int e = blockIdx.x * blockDim.x + threadIdx.x;
    if (e < E) {
        int s = ei[e];
        int d = ei[E + e];
        int pos = atomicAdd(&g_cursor[d], 1);
        g_csrc[pos] = s;
    }
}

// ---------------- tensor-core GEMM ------------------------------------------
// Y[n,F] = (relu?(A[n,128]) @ W[128,F]) * dinv[row],  bf16x3 split for fp32.
// Warp tiling 4(M) x 2(N): Mw=32 rows, Nw=F/2 cols per warp.

__device__ __forceinline__ unsigned packbf(float a, float b) {
    __nv_bfloat162 p = __floats2bfloat162_rn(a, b);
    return *reinterpret_cast<unsigned*>(&p);
}

__device__ __forceinline__ void mma_bf16(float* c,
                                         unsigned a0, unsigned a1, unsigned a2, unsigned a3,
                                         unsigned b0, unsigned b1) {
    asm volatile(
        "mma.sync.aligned.m16n8k16.row.col.f32.bf16.bf16.f32 "
        "{%0,%1,%2,%3}, {%4,%5,%6,%7}, {%8,%9}, {%0,%1,%2,%3};"
        : "+f"(c[0]), "+f"(c[1]), "+f"(c[2]), "+f"(c[3])
        : "r"(a0), "r"(a1), "r"(a2), "r"(a3), "r"(b0), "r"(b1));
}

template <int F, bool RELU>
__global__ __launch_bounds__(256)
void gemm_tc(const float* __restrict__ A,
             const __nv_bfloat16* __restrict__ Wh,
             const __nv_bfloat16* __restrict__ Wl, int n) {
    extern __shared__ unsigned char smraw[];
    __nv_bfloat16* sWh = (__nv_bfloat16*)smraw;        // F * KPAD
    __nv_bfloat16* sWl = sWh + F * KPAD;
    __nv_bfloat16* sAh = sWl + F * KPAD;               // 128 * KPAD
    __nv_bfloat16* sAl = sAh + 128 * KPAD;

    const int NT = F / 16;                             // 8-wide n-tiles per warp
    int tid = threadIdx.x;
    int wid = tid >> 5, lane = tid & 31;
    int g = lane >> 2, t = lane & 3;
    int wm = wid >> 1;
    int wn = wid & 1;
    int arow = wm * 32;
    int bcol0 = wn * (F / 2);

    {
        const unsigned* gwh = (const unsigned*)Wh;
        const unsigned* gwl = (const unsigned*)Wl;
        for (int i = tid; i < F * 64; i += 256) {
            int r = i >> 6, c = i & 63;
            ((unsigned*)(sWh + r * KPAD))[c] = gwh[i];
            ((unsigned*)(sWl + r * KPAD))[c] = gwl[i];
        }
    }

    int ntiles = (n + 127) >> 7;
    for (int tile = blockIdx.x; tile < ntiles; tile += gridDim.x) {
        __syncthreads();
        int r0 = tile * 128;

        for (int i = tid; i < 4096; i += 256) {
            int r = i >> 5, c4 = i & 31;
            int row = r0 + r;
            float4 v = make_float4(0.f, 0.f, 0.f, 0.f);
            if (row < n) v = *(const float4*)(A + (size_t)row * 128 + c4 * 4);
            if (RELU) {
                v.x = fmaxf(v.x, 0.f); v.y = fmaxf(v.y, 0.f);
                v.z = fmaxf(v.z, 0.f); v.w = fmaxf(v.w, 0.f);
            }
            __nv_bfloat16 h0 = __float2bfloat16(v.x), h1 = __float2bfloat16(v.y);
            __nv_bfloat16 h2 = __float2bfloat16(v.z), h3 = __float2bfloat16(v.w);
            float l0 = v.x - __bfloat162float(h0), l1 = v.y - __bfloat162float(h1);
            float l2 = v.z - __bfloat162float(h2), l3 = v.w - __bfloat162float(h3);
            unsigned h01, h23;
            { __nv_bfloat162 p0 = {h0, h1}; h01 = *reinterpret_cast<unsigned*>(&p0);
              __nv_bfloat162 p1 = {h2, h3}; h23 = *reinterpret_cast<unsigned*>(&p1); }
            unsigned l01 = packbf(l0, l1), l23 = packbf(l2, l3);
            *reinterpret_cast<uint2*>(sAh + r * KPAD + c4 * 4) = make_uint2(h01, h23);
            *reinterpret_cast<uint2*>(sAl + r * KPAD + c4 * 4) = make_uint2(l01, l23);
        }
        __syncthreads();

        float acc[2][NT][4];
        #pragma unroll
        for (int rb = 0; rb < 2; rb++)
            #pragma unroll
            for (int j = 0; j < NT; j++) {
                acc[rb][j][0] = 0.f; acc[rb][j][1] = 0.f;
                acc[rb][j][2] = 0.f; acc[rb][j][3] = 0.f;
            }

        #pragma unroll
        for (int kk = 0; kk < 128; kk += 16) {
            unsigned ah[2][4], al[2][4];
            #pragma unroll
            for (int rb = 0; rb < 2; rb++) {
                int br = arow + rb * 16;
                ah[rb][0] = *(const unsigned*)(sAh + (br + g)     * KPAD + kk + 2 * t);
                ah[rb][1] = *(const unsigned*)(sAh + (br + g + 8) * KPAD + kk + 2 * t);
                ah[rb][2] = *(const unsigned*)(sAh + (br + g)     * KPAD + kk + 8 + 2 * t);
                ah[rb][3] = *(const unsigned*)(sAh + (br + g + 8) * KPAD + kk + 8 + 2 * t);
                al[rb][0] = *(const unsigned*)(sAl + (br + g)     * KPAD + kk + 2 * t);
                al[rb][1] = *(const unsigned*)(sAl + (br + g + 8) * KPAD + kk + 2 * t);
                al[rb][2] = *(const unsigned*)(sAl + (br + g)     * KPAD + kk + 8 + 2 * t);
                al[rb][3] = *(const unsigned*)(sAl + (br + g + 8) * KPAD + kk + 8 + 2 * t);
            }
            #pragma unroll
            for (int j = 0; j < NT; j++) {
                int bn = bcol0 + j * 8 + g;
                unsigned b0h = *(const unsigned*)(sWh + bn * KPAD + kk + 2 * t);
                unsigned b1h = *(const unsigned*)(sWh + bn * KPAD + kk + 8 + 2 * t);
                unsigned b0l = *(const unsigned*)(sWl + bn * KPAD + kk + 2 * t);
                unsigned b1l = *(const unsigned*)(sWl + bn * KPAD + kk + 8 + 2 * t);
                #pragma unroll
                for (int rb = 0; rb < 2; rb++) {
                    mma_bf16(acc[rb][j], ah[rb][0], ah[rb][1], ah[rb][2], ah[rb][3], b0h, b1h);
                    mma_bf16(acc[rb][j], ah[rb][0], ah[rb][1], ah[rb][2], ah[rb][3], b0l, b1l);
                    mma_bf16(acc[rb][j], al[rb][0], al[rb][1], al[rb][2], al[rb][3], b0h, b1h);
                }
            }
        }

        #pragma unroll
        for (int rb = 0; rb < 2; rb++) {
            int row0 = r0 + arow + rb * 16 + g;
            int row1 = row0 + 8;
            float d0 = (row0 < n) ? g_dinv[row0] : 0.f;
            float d1 = (row1 < n) ? g_dinv[row1] : 0.f;
            #pragma unroll
            for (int j = 0; j < NT; j++) {
                int col = bcol0 + j * 8 + 2 * t;
                if (row0 < n) {
                    float2 o = make_float2(acc[rb][j][0] * d0, acc[rb][j][1] * d0);
                    *(float2*)(g_Y + (size_t)row0 * F + col) = o;
                }
                if (row1 < n) {
                    float2 o = make_float2(acc[rb][j][2] * d1, acc[rb][j][3] * d1);
                    *(float2*)(g_Y + (size_t)row1 * F + col) = o;
                }
            }
        }
    }
}

// ---------------- aggregation: out[i] = dinv[i]*(Y[i] + sum Y[src]) + b ----
template <int F>
__global__ __launch_bounds__(256)
void agg_k(const float* __restrict__ bias, float* __restrict__ out, int n) {
    const int L = F / 4;
    int lane = threadIdx.x & (L - 1);
    int node = (blockIdx.x * blockDim.x + threadIdx.x) / L;
    if (node >= n) return;

    unsigned mask;
    if (L == 32) mask = 0xffffffffu;
    else         mask = 0xffffu << (((threadIdx.x & 31) >> 4) << 4);

    int s = g_rowptr[node];
    int e = g_rowptr[node + 1];

    float4 a0 = *(const float4*)(g_Y + (size_t)node * F + lane * 4);  // self loop
    float4 a1 = make_float4(0.f, 0.f, 0.f, 0.f);
    float4 a2 = make_float4(0.f, 0.f, 0.f, 0.f);
    float4 a3 = make_float4(0.f, 0.f, 0.f, 0.f);

    for (int base = s; base < e; base += L) {
        int idx = base + lane;
        int v = (idx < e) ? g_csrc[idx] : 0;
        int cnt = min(L, e - base);
        int tt = 0;
        for (; tt + 4 <= cnt; tt += 4) {
            int s0 = __shfl_sync(mask, v, tt,     L);
            int s1 = __shfl_sync(mask, v, tt + 1, L);
            int s2 = __shfl_sync(mask, v, tt + 2, L);
            int s3 = __shfl_sync(mask, v, tt + 3, L);
            float4 y0 = *(const float4*)(g_Y + (size_t)s0 * F + lane * 4);
            float4 y1 = *(const float4*)(g_Y + (size_t)s1 * F + lane * 4);
            float4 y2 = *(const float4*)(g_Y + (size_t)s2 * F + lane * 4);
            float4 y3 = *(const float4*)(g_Y + (size_t)s3 * F + lane * 4);
            a0.x += y0.x; a0.y += y0.y; a0.z += y0.z; a0.w += y0.w;
            a1.x += y1.x; a1.y += y1.y; a1.z += y1.z; a1.w += y1.w;
            a2.x += y2.x; a2.y += y2.y; a2.z += y2.z; a2.w += y2.w;
            a3.x += y3.x; a3.y += y3.y; a3.z += y3.z; a3.w += y3.w;
        }
        for (; tt < cnt; tt++) {
            int sc = __shfl_sync(mask, v, tt, L);
            float4 yv = *(const float4*)(g_Y + (size_t)sc * F + lane * 4);
            a0.x += yv.x; a0.y += yv.y; a0.z += yv.z; a0.w += yv.w;
        }
    }

    float4 acc;
    acc.x = (a0.x + a1.x) + (a2.x + a3.x);
    acc.y = (a0.y + a1.y) + (a2.y + a3.y);
    acc.z = (a0.z + a1.z) + (a2.z + a3.z);
    acc.w = (a0.w + a1.w) + (a2.w + a3.w);

    float d = g_dinv[node];
    float4 bb = *(const float4*)(bias + lane * 4);
    float4 o;
    o.x = fmaf(acc.x, d, bb.x);
    o.y = fmaf(acc.y, d, bb.y);
    o.z = fmaf(acc.z, d, bb.z);
    o.w = fmaf(acc.w, d, bb.w);
    *(float4*)(out + (size_t)node * F + lane * 4) = o;
}

// ---------------- launch -----------------------------------------------------

extern "C" void kernel_launch(void* const* d_in, const int* in_sizes, int n_in,
                              void* d_out, int out_size) {
    const float* x  = (const float*)d_in[0];
    const int*   ei = (const int*)d_in[1];   // int32
    const float* W1 = (const float*)d_in[2];
    const float* b1 = (const float*)d_in[3];
    const float* W2 = (const float*)d_in[4];
    const float* b2 = (const float*)d_in[5];
    const float* W3 = (const float*)d_in[6];
    const float* b3 = (const float*)d_in[7];
    float* out = (float*)d_out;

    float* hH = nullptr;
    cudaGetSymbolAddress((void**)&hH, g_H);
    __nv_bfloat16 *w1h, *w1l, *w2h, *w2l, *w3h, *w3l;
    cudaGetSymbolAddress((void**)&w1h, g_W1h);
    cudaGetSymbolAddress((void**)&w1l, g_W1l);
    cudaGetSymbolAddress((void**)&w2h, g_W2h);
    cudaGetSymbolAddress((void**)&w2l, g_W2l);
    cudaGetSymbolAddress((void**)&w3h, g_W3h);
    cudaGetSymbolAddress((void**)&w3l, g_W3l);

    int n = in_sizes[0] / 128;
    int E = in_sizes[1] / 2;

    const int SMEM128 = 4 * KPAD * (128 + 128);  // 139264 B
    const int SMEM64  = 4 * KPAD * (64  + 128);  // 104448 B
    cudaFuncSetAttribute(gemm_tc<128, false>, cudaFuncAttributeMaxDynamicSharedMemorySize, SMEM128);
    cudaFuncSetAttribute(gemm_tc<128, true>,  cudaFuncAttributeMaxDynamicSharedMemorySize, SMEM128);
    cudaFuncSetAttribute(gemm_tc<64,  true>,  cudaFuncAttributeMaxDynamicSharedMemorySize, SMEM64);

    int nbE = (E + 255) / 256;
    int nbS = (n + 1023) / 1024;   // 49 <= 64

    // --- CSR build + weight conversion: 4 kernels ---
    count_k<<<nbE, 256>>>(ei, E);
    scanconv_k<<<nbS + CONVB, 1024>>>(n, nbS, W1, W2, W3);
    scan_final_k<<<nbS, 1024>>>(n, nbS);
    fill_k<<<nbE, 256>>>(ei, E);

    int gAgg128 = ((n * 32) + 255) / 256;
    int gAgg64  = ((n * 16) + 255) / 256;

    // --- layer 1 ---  (launch idx 4 = gemm1, 5 = agg1 -> ncu samples agg1)
    gemm_tc<128, false><<<148, 256, SMEM128>>>(x, w1h, w1l, n);
    agg_k<128><<<gAgg128, 256>>>(b1, hH, n);

    // --- layer 2 ---
    gemm_tc<128, true><<<148, 256, SMEM128>>>(hH, w2h, w2l, n);
    agg_k<128><<<gAgg128, 256>>>(b2, hH, n);

    // --- layer 3 ---
    gemm_tc<64, true><<<148, 256, SMEM64>>>(hH, w3h, w3l, n);
    agg_k<64><<<gAgg64, 256>>>(b3, out, n);
}